// round 16
// baseline (speedup 1.0000x reference)
#include <cuda_runtime.h>
#include <cuda_fp16.h>
#include <cstdint>

// ---------------------------------------------------------------------------
// MaskedCrossAttention — single-fp16 GEMMs on mma.sync (at the structural
// ~630 MAC/cyc/SM legacy-HMMA wall). R16: f32x2-packed attention inner loops
// (identical arithmetic), all prep fused into one launch.
// ---------------------------------------------------------------------------

constexpr int DIM    = 2048;
constexpr int DIMV   = 1024;
constexpr int INNER_ = 1024;
constexpr int DH     = 64;
constexpr int HEADS_ = 16;
constexpr int B_     = 4;
constexpr int T_     = 2048;
constexpr int NM     = 8;
constexpr int NV     = 64;
constexpr int J_     = NM * NV;     // 512
constexpr float LN_EPS = 1e-5f;
constexpr float WSCALE = 1024.0f;   // weight pre-scale

// GEMM tiling
constexpr int BM = 128, BN = 128, BK = 64;
constexpr int A_OFF = 0;
constexpr int B_OFF = BM * BK * 2;               // 16384
constexpr int STAGE_BYTES = B_OFF + BN * BK * 2; // 32768
constexpr int NSTAGE = 3;
constexpr int SMEM_DYN = NSTAGE * STAGE_BYTES + 1024;  // 99328 -> 2 CTAs/SM

// attention smem layout (float units)
constexpr int AT_K_OFF = 0;                        // Ks[64][65]
constexpr int AT_V_OFF = NV * (DH + 1);            // 4160
constexpr int AT_Q_OFF = 2 * NV * (DH + 1);        // 8320; qs2 float2[8][8][64]
constexpr int AT_A_OFF = AT_Q_OFF + 8 * 8 * DH * 2;// 16512; as2 float2[8][8][64]
constexpr int ATTN_SMEM = (AT_A_OFF + 8 * 8 * NV * 2) * 4;  // 98816 bytes

// prep kernel block-range dispatch
constexpr int PREP_SCAN   = B_;                              // 4
constexpr int PREP_TOHALF = (B_ * J_ * DIMV) / 2048;         // 1024
constexpr int PREP_TQ     = (INNER_ / 32) * (DIM / 32);      // 2048
constexpr int PREP_TK     = (2 * INNER_ / 32) * (DIMV / 32); // 2048
constexpr int PREP_TO     = (DIM / 32) * (INNER_ / 32);      // 2048
constexpr int PREP_BLKS   = PREP_SCAN + PREP_TOHALF + PREP_TQ + PREP_TK + PREP_TO;

// ---- scratch (__device__ globals; runtime allocation forbidden) ----
__device__ __half g_yn [(size_t)B_ * T_ * DIM];
__device__ __half g_m  [(size_t)B_ * J_ * DIMV];
__device__ __half g_at [(size_t)B_ * T_ * INNER_];
__device__ __half g_wq [(size_t)INNER_ * DIM];        // WqT x1024
__device__ __half g_wk [(size_t)2 * INNER_ * DIMV];   // WkvT x1024
__device__ __half g_wo [(size_t)DIM * INNER_];        // WoutT x1024
__device__ __half g_q [(size_t)B_ * T_ * INNER_];     // q fp16
__device__ float g_kv[(size_t)B_ * J_ * 2 * INNER_];
__device__ int   g_tok[B_ * NM * T_];
__device__ int   g_cnt[B_ * NM];

// ---------------------------------------------------------------------------
__device__ __forceinline__ uint32_t smem_u32(const void* p) {
    uint32_t a;
    asm("{ .reg .u64 t; cvta.to.shared.u64 t, %1; cvt.u32.u64 %0, t; }"
        : "=r"(a) : "l"(p));
    return a;
}
#define CPASYNC16(dst, src) \
    asm volatile("cp.async.cg.shared.global [%0], [%1], 16;\n" \
                 :: "r"(dst), "l"(src) : "memory")
#define CP_COMMIT() asm volatile("cp.async.commit_group;" ::: "memory")
#define CP_WAIT(n)  asm volatile("cp.async.wait_group %0;" :: "n"(n) : "memory")

#define LDSM4(r, a) \
    asm volatile("ldmatrix.sync.aligned.m8n8.x4.shared.b16 {%0,%1,%2,%3}, [%4];" \
        : "=r"((r)[0]), "=r"((r)[1]), "=r"((r)[2]), "=r"((r)[3]) : "r"(a))

#define MMAF16(d, a, b0, b1) \
    asm volatile("mma.sync.aligned.m16n8k16.row.col.f32.f16.f16.f32 " \
        "{%0,%1,%2,%3}, {%4,%5,%6,%7}, {%8,%9}, {%0,%1,%2,%3};" \
        : "+f"((d)[0]), "+f"((d)[1]), "+f"((d)[2]), "+f"((d)[3]) \
        : "r"((a)[0]), "r"((a)[1]), "r"((a)[2]), "r"((a)[3]), "r"(b0), "r"(b1))

#define FMA2(acc, a, b) \
    asm("fma.rn.f32x2 %0, %1, %2, %0;" : "+l"(acc) : "l"(a), "l"(b))

__device__ __forceinline__ uint32_t swz(uint32_t off) {
    return off ^ ((off >> 3) & 0x70);
}
__device__ __forceinline__ unsigned long long pack2(float lo, float hi) {
    unsigned long long r;
    asm("mov.b64 %0, {%1, %2};" : "=l"(r) : "f"(lo), "f"(hi));
    return r;
}
__device__ __forceinline__ void unpack2(unsigned long long v, float& lo, float& hi) {
    asm("mov.b64 {%0, %1}, %2;" : "=f"(lo), "=f"(hi) : "l"(v));
}

struct GemmP {
    const __half *A, *B;
    void* C;
    int N, K, tilesx;
    float alpha;
    int chalf;      // 1: store C as fp16, 0: fp32
};

// ---------------------------------------------------------------------------
// stage loader: A [128 x 64 fp16] + B [128 x 64 fp16], SW128 rows.
// ---------------------------------------------------------------------------
__device__ __forceinline__ void load_stage(
    uint32_t sb,
    const __half* __restrict__ A, const __half* __restrict__ B,
    int k0, int K, int tid)
{
#pragma unroll
    for (int i = 0; i < 4; i++) {            // 1024 16B units each
        int u = tid + i * 256;
        int row = u >> 3, cb = (u & 7) * 16;
        uint32_t off = swz((uint32_t)(row * 128 + cb));
        CPASYNC16(sb + A_OFF + off, (const char*)(A + (size_t)row * K + k0) + cb);
        CPASYNC16(sb + B_OFF + off, (const char*)(B + (size_t)row * K + k0) + cb);
    }
}

// ---------------------------------------------------------------------------
// GEMM: C[M,N] = alpha * A[M,K] @ B[N,K]^T   (fp16 x fp16 -> fp32/fp16)
// 128x128 CTA tile, 256 threads (8 warps 2x4), warp tile 64x32, 3 stages,
// 2 CTAs/SM. Two problems per launch.
// ---------------------------------------------------------------------------
__global__ __launch_bounds__(256, 2) void gemm_mma(GemmP p0, GemmP p1, int nblk0)
{
    extern __shared__ char dsm[];
    uint32_t base = (smem_u32(dsm) + 1023) & ~1023u;
    int tid = threadIdx.x, wid = tid >> 5, lane = tid & 31;
    int wm = wid >> 2, wn = wid & 3;         // 2 x 4 warp grid

    GemmP p = (blockIdx.x < nblk0) ? p0 : p1;
    int lb = (blockIdx.x < nblk0) ? blockIdx.x : blockIdx.x - nblk0;
    int bx = lb % p.tilesx, by = lb / p.tilesx;
    int K = p.K, N = p.N;

    const __half* Ab = p.A + (size_t)by * BM * K;
    const __half* Bb = p.B + (size_t)bx * BN * K;
    int nch = K / BK;

    float acc[4][4][4];
#pragma unroll
    for (int mi = 0; mi < 4; mi++)
#pragma unroll
        for (int ni = 0; ni < 4; ni++)
#pragma unroll
            for (int r = 0; r < 4; r++) acc[mi][ni][r] = 0.f;

    // prologue: fill stages 0 and 1
    load_stage(base, Ab, Bb, 0, K, tid);
    CP_COMMIT();
    load_stage(base + STAGE_BYTES, Ab, Bb, BK, K, tid);
    CP_COMMIT();

    // per-lane ldmatrix address components
    int ra  = wm * 64 + (lane & 15);                    // A row
    uint32_t cba = (uint32_t)(lane & 16);               // A byte col sel
    int rb  = wn * 32 + (lane & 7) + ((lane >> 1) & 8); // B row base
    uint32_t cbb = (uint32_t)((lane & 8) << 1);         // B byte col sel

    int slot = 0;
    for (int i = 0; i < nch; i++) {
        uint32_t sb = base + (uint32_t)slot * STAGE_BYTES;
        if (i + 2 < nch) { CP_WAIT(1); } else { CP_WAIT(0); }
        __syncthreads();
        if (i + 2 < nch) {  // refill the slot freed by chunk i-1
            int ns = slot + 2; if (ns >= NSTAGE) ns -= NSTAGE;
            load_stage(base + (uint32_t)ns * STAGE_BYTES,
                       Ab, Bb, (i + 2) * BK, K, tid);
            CP_COMMIT();
        }
#pragma unroll
        for (int ks = 0; ks < 4; ks++) {
            uint32_t kb = (uint32_t)(ks * 32);
            uint32_t ahr[4][4];
#pragma unroll
            for (int mi = 0; mi < 4; mi++) {
                uint32_t off = swz((uint32_t)((ra + mi * 16) * 128) + kb + cba);
                LDSM4(ahr[mi], sb + A_OFF + off);
            }
#pragma unroll
            for (int nb = 0; nb < 2; nb++) {
                uint32_t bh[4];
                uint32_t off = swz((uint32_t)((rb + nb * 16) * 128) + kb + cbb);
                LDSM4(bh, sb + B_OFF + off);
#pragma unroll
                for (int mi = 0; mi < 4; mi++) {
                    MMAF16(acc[mi][nb * 2],     ahr[mi], bh[0], bh[1]);
                    MMAF16(acc[mi][nb * 2 + 1], ahr[mi], bh[2], bh[3]);
                }
            }
        }
        if (++slot >= NSTAGE) slot = 0;
    }

    // epilogue
    int r0 = by * BM + wm * 64;
    int c0 = bx * BN + wn * 32;
    float alpha = p.alpha;
    if (p.chalf) {
        __half* Ch = (__half*)p.C;
#pragma unroll
        for (int mi = 0; mi < 4; mi++)
#pragma unroll
            for (int ni = 0; ni < 4; ni++) {
                int row = r0 + mi * 16 + (lane >> 2);
                int col = c0 + ni * 8 + (lane & 3) * 2;
                __half2 h0 = __floats2half2_rn(acc[mi][ni][0] * alpha,
                                               acc[mi][ni][1] * alpha);
                __half2 h1 = __floats2half2_rn(acc[mi][ni][2] * alpha,
                                               acc[mi][ni][3] * alpha);
                *(__half2*)(Ch + (size_t)row * N + col)       = h0;
                *(__half2*)(Ch + (size_t)(row + 8) * N + col) = h1;
            }
    } else {
        float* Cf = (float*)p.C;
#pragma unroll
        for (int mi = 0; mi < 4; mi++)
#pragma unroll
            for (int ni = 0; ni < 4; ni++) {
                int row = r0 + mi * 16 + (lane >> 2);
                int col = c0 + ni * 8 + (lane & 3) * 2;
                float2 v0 = make_float2(acc[mi][ni][0] * alpha, acc[mi][ni][1] * alpha);
                float2 v1 = make_float2(acc[mi][ni][2] * alpha, acc[mi][ni][3] * alpha);
                *(float2*)(Cf + (size_t)row * N + col)       = v0;
                *(float2*)(Cf + (size_t)(row + 8) * N + col) = v1;
            }
    }
}

// ---------------------------------------------------------------------------
// LayerNorm -> fp16 directly.
// ---------------------------------------------------------------------------
__global__ __launch_bounds__(256) void ln_kernel(
    const float* __restrict__ y, const float* __restrict__ w,
    const float* __restrict__ bia)
{
    int row = blockIdx.x;
    const float* x = y + (size_t)row * DIM;
    float v[8], s = 0.f, s2 = 0.f;
#pragma unroll
    for (int i = 0; i < 8; i++) {
        v[i] = x[threadIdx.x + i * 256];
        s += v[i]; s2 += v[i] * v[i];
    }
#pragma unroll
    for (int off = 16; off; off >>= 1) {
        s  += __shfl_down_sync(0xffffffffu, s, off);
        s2 += __shfl_down_sync(0xffffffffu, s2, off);
    }
    __shared__ float sm[2][8], stats[2];
    int lane = threadIdx.x & 31, wid = threadIdx.x >> 5;
    if (lane == 0) { sm[0][wid] = s; sm[1][wid] = s2; }
    __syncthreads();
    if (threadIdx.x == 0) {
        float ts = 0.f, ts2 = 0.f;
#pragma unroll
        for (int i = 0; i < 8; i++) { ts += sm[0][i]; ts2 += sm[1][i]; }
        float mu = ts / DIM, var = ts2 / DIM - mu * mu;
        stats[0] = mu; stats[1] = rsqrtf(var + LN_EPS);
    }
    __syncthreads();
    float mu = stats[0], rstd = stats[1];
#pragma unroll
    for (int i = 0; i < 8; i++) {
        int idx = threadIdx.x + i * 256;
        float val = (v[i] - mu) * rstd * w[idx] + bia[idx];
        g_yn[(size_t)row * DIM + idx] = __float2half(val);
    }
}

// ---------------------------------------------------------------------------
// fused prep: scan+build | media tohalf | 3 weight transposes, by block range.
// ---------------------------------------------------------------------------
__device__ __forceinline__ void do_transpose(
    const float* __restrict__ W, __half* __restrict__ Th,
    int K, int N, int tileIdx, float* tbuf /* 32*33 floats */)
{
    float (*t)[33] = (float(*)[33])tbuf;
    int tilesx = N / 32;
    int nb = (tileIdx % tilesx) * 32;
    int kb = (tileIdx / tilesx) * 32;
    int tx = threadIdx.x & 31, ty = threadIdx.x >> 5;
#pragma unroll
    for (int r = 0; r < 32; r += 8)
        t[ty + r][tx] = W[(size_t)(kb + ty + r) * N + nb + tx];
    __syncthreads();
#pragma unroll
    for (int r = 0; r < 32; r += 8) {
        float v = t[tx][ty + r] * WSCALE;
        Th[(size_t)(nb + ty + r) * K + kb + tx] = __float2half(v);
    }
}

__global__ __launch_bounds__(256) void prep_kernel(
    const void* __restrict__ locp, const float* __restrict__ media,
    const float* __restrict__ Wq, const float* __restrict__ Wkv,
    const float* __restrict__ Wout)
{
    __shared__ float tbuf[32 * 33];
    __shared__ int cnt_s[NM];
    __shared__ int wsum[8];
    int blk = blockIdx.x, tid = threadIdx.x;

    if (blk < PREP_SCAN) {
        // --- inclusive scan + token-list build for batch b = blk ---
        const unsigned int* u = (const unsigned int*)locp;
        int mode;
        if (u[0] == 0x3F800000u) mode = 2;
        else if (u[64] & 0xFFu)  mode = 1;
        else                     mode = 0;
        int b = blk;
        if (tid < NM) cnt_s[tid] = 0;
        int v[8], s = 0;
#pragma unroll
        for (int i = 0; i < 8; i++) {
            int g = b * T_ + tid * 8 + i;
            int bit;
            if (mode == 1)      bit = ((const unsigned char*)locp)[g] != 0;
            else if (mode == 2) bit = ((const float*)locp)[g] != 0.0f;
            else                bit = ((const int*)locp)[g] != 0;
            v[i] = bit; s += bit;
        }
        int lane = tid & 31, wid = tid >> 5, pre = s;
#pragma unroll
        for (int off = 1; off < 32; off <<= 1) {
            int n = __shfl_up_sync(0xffffffffu, pre, off);
            if (lane >= off) pre += n;
        }
        if (lane == 31) wsum[wid] = pre;
        __syncthreads();
        int woff = 0;
        for (int w = 0; w < wid; w++) woff += wsum[w];
        int tt = woff + pre - s;
#pragma unroll
        for (int i = 0; i < 8; i++) {
            tt += v[i];
            if (tt >= 1 && tt <= NM) {
                int idx = atomicAdd(&cnt_s[tt - 1], 1);
                g_tok[(b * NM + tt - 1) * T_ + idx] = tid * 8 + i;
            }
        }
        __syncthreads();
        if (tid < NM) g_cnt[b * NM + tid] = cnt_s[tid];
    } else if (blk < PREP_SCAN + PREP_TOHALF) {
        int base = (blk - PREP_SCAN) * 2048;
#pragma unroll
        for (int i = 0; i < 8; i++) {
            int e = base + i * 256 + tid;
            g_m[e] = __float2half(media[e]);
        }
    } else if (blk < PREP_SCAN + PREP_TOHALF + PREP_TQ) {
        do_transpose(Wq, g_wq, DIM, INNER_,
                     blk - PREP_SCAN - PREP_TOHALF, tbuf);
    } else if (blk < PREP_SCAN + PREP_TOHALF + PREP_TQ + PREP_TK) {
        do_transpose(Wkv, g_wk, DIMV, 2 * INNER_,
                     blk - PREP_SCAN - PREP_TOHALF - PREP_TQ, tbuf);
    } else {
        do_transpose(Wout, g_wo, INNER_, DIM,
                     blk - PREP_SCAN - PREP_TOHALF - PREP_TQ - PREP_TK, tbuf);
    }
}

// ---------------------------------------------------------------------------
// masked attention, 8-token-tiled with f32x2-packed inner loops.
// q and alphas are stored DUPLICATED as float2 so broadcasts are LDS.64
// and feed fma.rn.f32x2 directly (identical arithmetic to the scalar form).
// ---------------------------------------------------------------------------
__global__ __launch_bounds__(256) void attn_kernel() {
    extern __shared__ float sm[];
    float  (*Ks)[DH + 1]   = (float(*)[DH + 1])(sm + AT_K_OFF);
    float  (*Vs)[DH + 1]   = (float(*)[DH + 1])(sm + AT_V_OFF);
    float2 (*qs2)[8][DH]   = (float2(*)[8][DH])(sm + AT_Q_OFF);
    float2 (*as2)[8][NV]   = (float2(*)[8][NV])(sm + AT_A_OFF);

    int bm = blockIdx.x;
    int b = bm >> 3, m = bm & 7;
    int h = blockIdx.y;
    int tid = threadIdx.x;
    for (int i = tid; i < NV * DH; i += 256) {
        int jj = i >> 6, d = i & 63;
        const float* kvrow = g_kv + (size_t)(b * J_ + m * NV + jj) * (2 * INNER_);
        Ks[jj][d] = kvrow[h * DH + d];
        Vs[jj][d] = kvrow[INNER_ + h * DH + d];
    }
    __syncthreads();
    int cnt = g_cnt[b * NM + m];
    int wid = tid >> 5, lane = tid & 31;
    int j0 = lane, j1 = lane + 32;
    const int* toklist = g_tok + (b * NM + m) * T_;

    for (int basei = wid * 8; basei < cnt; basei += 64) {
        int t[8];
#pragma unroll
        for (int tk = 0; tk < 8; tk++) {
            int idx = basei + tk;
            t[tk] = toklist[idx < cnt ? idx : basei];
        }
        // q tiles: fp16 global -> duplicated float2 smem
#pragma unroll
        for (int tk = 0; tk < 8; tk++) {
            const __half* qrow = g_q + (size_t)(b * T_ + t[tk]) * INNER_ + h * DH;
            float q0 = __half2float(qrow[lane]);
            float q1 = __half2float(qrow[lane + 32]);
            qs2[wid][tk][lane]      = make_float2(q0, q0);
            qs2[wid][tk][lane + 32] = make_float2(q1, q1);
        }
        __syncwarp();

        unsigned long long s01[8];
#pragma unroll
        for (int tk = 0; tk < 8; tk++) s01[tk] = 0ull;
#pragma unroll 4
        for (int d = 0; d < DH; d++) {
            unsigned long long kp = pack2(Ks[j0][d], Ks[j1][d]);
#pragma unroll
            for (int tk = 0; tk < 8; tk++) {
                unsigned long long q2 =
                    *(const unsigned long long*)&qs2[wid][tk][d];
                FMA2(s01[tk], q2, kp);
            }
        }
#pragma unroll
        for (int tk = 0; tk < 8; tk++) {
            float s0, s1;
            unpack2(s01[tk], s0, s1);
            float mx = fmaxf(s0, s1);
#pragma unroll
            for (int off = 16; off; off >>= 1)
                mx = fmaxf(mx, __shfl_xor_sync(0xffffffffu, mx, off));
            float e0 = expf(s0 - mx), e1 = expf(s1 - mx);
            float ss = e0 + e1;
#pragma unroll
            for (int off = 16; off; off >>= 1)
                ss += __shfl_xor_sync(0xffffffffu, ss, off);
            float inv = 1.0f / ss;
            float a0 = e0 * inv, a1 = e1 * inv;
            as2[wid][tk][j0] = make_float2(a0, a0);
            as2[wid][tk][j1] = make_float2(a1, a1);
        }
        __syncwarp();

        unsigned long long o01[8];
#pragma unroll
        for (int tk = 0; tk < 8; tk++) o01[tk] = 0ull;
#pragma unroll 4
        for (int j = 0; j < NV; j++) {
            unsigned long long vp = pack2(Vs[j][lane], Vs[j][lane + 32]);
#pragma unroll
            for (int tk = 0; tk < 8; tk++) {
                unsigned long long a2 =
                    *(const unsigned long long*)&as2[wid][tk][j];
                FMA2(o01[tk], a2, vp);
            }
        }
#pragma unroll
        for (int tk = 0; tk < 8; tk++) {
            if (basei + tk < cnt) {
                float o0, o1;
                unpack2(o01[tk], o0, o1);
                size_t ob = (size_t)(b * T_ + t[tk]) * INNER_ + h * DH;
                g_at[ob + lane]      = __float2half(o0);
                g_at[ob + lane + 32] = __float2half(o1);
            }
        }
        __syncwarp();
    }
}

// ---------------------------------------------------------------------------
extern "C" void kernel_launch(void* const* d_in, const int* in_sizes, int n_in,
                              void* d_out, int out_size)
{
    const float* y     = (const float*)d_in[0];
    const float* media = (const float*)d_in[1];
    const void*  loc   = d_in[2];
    const float* lnw   = (const float*)d_in[3];
    const float* lnb   = (const float*)d_in[4];
    const float* Wq    = (const float*)d_in[5];
    const float* Wkv   = (const float*)d_in[6];
    const float* Wout  = (const float*)d_in[7];
    float*       out   = (float*)d_out;

    static bool attr_set = false;   // host-side config only
    if (!attr_set) {
        cudaFuncSetAttribute(gemm_mma,
            cudaFuncAttributeMaxDynamicSharedMemorySize, SMEM_DYN);
        cudaFuncSetAttribute(attn_kernel,
            cudaFuncAttributeMaxDynamicSharedMemorySize, ATTN_SMEM);
        attr_set = true;
    }

    __half *yn, *m, *at, *wq, *wk, *wo, *q;
    float *kv;
    cudaGetSymbolAddress((void**)&yn, g_yn);
    cudaGetSymbolAddress((void**)&m,  g_m);
    cudaGetSymbolAddress((void**)&at, g_at);
    cudaGetSymbolAddress((void**)&wq, g_wq);
    cudaGetSymbolAddress((void**)&wk, g_wk);
    cudaGetSymbolAddress((void**)&wo, g_wo);
    cudaGetSymbolAddress((void**)&q,  g_q);
    cudaGetSymbolAddress((void**)&kv, g_kv);

    ln_kernel<<<B_ * T_, 256>>>(y, lnw, lnb);
    prep_kernel<<<PREP_BLKS, 256>>>(loc, media, Wq, Wkv, Wout);

    // fused launch: GEMM1 (q = yn @ WqT^T * 0.125, fp16 out) + GEMM2 (kv fp32 out)
    GemmP p1 { yn, wq, (void*)q, INNER_, DIM, INNER_ / BN, 0.125f / WSCALE, 1 };
    int nblk1 = (INNER_ / BN) * ((B_ * T_) / BM);       // 8 * 64 = 512
    GemmP p2 { m, wk, (void*)kv, 2 * INNER_, DIMV, 2 * INNER_ / BN, 1.0f / WSCALE, 0 };
    int nblk2 = (2 * INNER_ / BN) * ((B_ * J_) / BM);   // 16 * 16 = 256
    gemm_mma<<<nblk1 + nblk2, 256, SMEM_DYN>>>(p1, p2, nblk1);

    attn_kernel<<<dim3(B_ * NM, HEADS_), 256, ATTN_SMEM>>>();

    // GEMM3: out = attn @ WoutT^T (fp32 out)
    GemmP p3 { at, wo, (void*)out, DIM, INNER_, DIM / BN, 1.0f / WSCALE, 0 };
    int nblk3 = (DIM / BN) * ((B_ * T_) / BM);          // 16 * 64 = 1024
    gemm_mma<<<nblk3, 256, SMEM_DYN>>>(p3, p3, nblk3);
}

// round 17
// speedup vs baseline: 1.3546x; 1.3546x over previous
#include <cuda_runtime.h>
#include <cuda_fp16.h>
#include <cstdint>

// ---------------------------------------------------------------------------
// MaskedCrossAttention — single-fp16 GEMMs on mma.sync (~630 MAC/cyc/SM wall).
// R17: attention itself moved to mma.sync (flash-style: S-frag reused as
// P-frag, V stored transposed so PV uses the same ldmatrix recipe as QK).
// kv produced in fp16 by GEMM2. Fused prep launch retained.
// ---------------------------------------------------------------------------

constexpr int DIM    = 2048;
constexpr int DIMV   = 1024;
constexpr int INNER_ = 1024;
constexpr int DH     = 64;
constexpr int HEADS_ = 16;
constexpr int B_     = 4;
constexpr int T_     = 2048;
constexpr int NM     = 8;
constexpr int NV     = 64;
constexpr int J_     = NM * NV;     // 512
constexpr float LN_EPS = 1e-5f;
constexpr float WSCALE = 1024.0f;   // weight pre-scale

// GEMM tiling
constexpr int BM = 128, BN = 128, BK = 64;
constexpr int A_OFF = 0;
constexpr int B_OFF = BM * BK * 2;               // 16384
constexpr int STAGE_BYTES = B_OFF + BN * BK * 2; // 32768
constexpr int NSTAGE = 3;
constexpr int SMEM_DYN = NSTAGE * STAGE_BYTES + 1024;  // 99328 -> 2 CTAs/SM

// attention smem layout (bytes)
constexpr int ATK_OFF = 0;        // Ks [64 keys][128B] swizzled
constexpr int ATV_OFF = 8192;     // Vt [64 dims][128B] swizzled (transposed V)
constexpr int ATQ_OFF = 16384;    // Qs: 4 warps x [16 rows][128B]

// prep kernel block-range dispatch
constexpr int PREP_SCAN   = B_;                              // 4
constexpr int PREP_TOHALF = (B_ * J_ * DIMV) / 2048;         // 1024
constexpr int PREP_TQ     = (INNER_ / 32) * (DIM / 32);      // 2048
constexpr int PREP_TK     = (2 * INNER_ / 32) * (DIMV / 32); // 2048
constexpr int PREP_TO     = (DIM / 32) * (INNER_ / 32);      // 2048
constexpr int PREP_BLKS   = PREP_SCAN + PREP_TOHALF + PREP_TQ + PREP_TK + PREP_TO;

// ---- scratch (__device__ globals; runtime allocation forbidden) ----
__device__ __half g_yn [(size_t)B_ * T_ * DIM];
__device__ __half g_m  [(size_t)B_ * J_ * DIMV];
__device__ __half g_at [(size_t)B_ * T_ * INNER_];
__device__ __half g_wq [(size_t)INNER_ * DIM];        // WqT x1024
__device__ __half g_wk [(size_t)2 * INNER_ * DIMV];   // WkvT x1024
__device__ __half g_wo [(size_t)DIM * INNER_];        // WoutT x1024
__device__ __half g_q  [(size_t)B_ * T_ * INNER_];    // q fp16
__device__ __half g_kv [(size_t)B_ * J_ * 2 * INNER_];// kv fp16
__device__ int   g_tok[B_ * NM * T_];
__device__ int   g_cnt[B_ * NM];

// ---------------------------------------------------------------------------
__device__ __forceinline__ uint32_t smem_u32(const void* p) {
    uint32_t a;
    asm("{ .reg .u64 t; cvta.to.shared.u64 t, %1; cvt.u32.u64 %0, t; }"
        : "=r"(a) : "l"(p));
    return a;
}
#define CPASYNC16(dst, src) \
    asm volatile("cp.async.cg.shared.global [%0], [%1], 16;\n" \
                 :: "r"(dst), "l"(src) : "memory")
#define CP_COMMIT() asm volatile("cp.async.commit_group;" ::: "memory")
#define CP_WAIT(n)  asm volatile("cp.async.wait_group %0;" :: "n"(n) : "memory")

#define LDSM4(r, a) \
    asm volatile("ldmatrix.sync.aligned.m8n8.x4.shared.b16 {%0,%1,%2,%3}, [%4];" \
        : "=r"((r)[0]), "=r"((r)[1]), "=r"((r)[2]), "=r"((r)[3]) : "r"(a))

#define MMAF16(d, a, b0, b1) \
    asm volatile("mma.sync.aligned.m16n8k16.row.col.f32.f16.f16.f32 " \
        "{%0,%1,%2,%3}, {%4,%5,%6,%7}, {%8,%9}, {%0,%1,%2,%3};" \
        : "+f"((d)[0]), "+f"((d)[1]), "+f"((d)[2]), "+f"((d)[3]) \
        : "r"((a)[0]), "r"((a)[1]), "r"((a)[2]), "r"((a)[3]), "r"(b0), "r"(b1))

__device__ __forceinline__ uint32_t swz(uint32_t off) {
    return off ^ ((off >> 3) & 0x70);
}
__device__ __forceinline__ uint32_t h2pack(float a, float b) {
    __half2 h = __floats2half2_rn(a, b);
    return *(uint32_t*)&h;
}

struct GemmP {
    const __half *A, *B;
    void* C;
    int N, K, tilesx;
    float alpha;
    int chalf;      // 1: store C as fp16, 0: fp32
};

// ---------------------------------------------------------------------------
// stage loader: A [128 x 64 fp16] + B [128 x 64 fp16], SW128 rows.
// ---------------------------------------------------------------------------
__device__ __forceinline__ void load_stage(
    uint32_t sb,
    const __half* __restrict__ A, const __half* __restrict__ B,
    int k0, int K, int tid)
{
#pragma unroll
    for (int i = 0; i < 4; i++) {            // 1024 16B units each
        int u = tid + i * 256;
        int row = u >> 3, cb = (u & 7) * 16;
        uint32_t off = swz((uint32_t)(row * 128 + cb));
        CPASYNC16(sb + A_OFF + off, (const char*)(A + (size_t)row * K + k0) + cb);
        CPASYNC16(sb + B_OFF + off, (const char*)(B + (size_t)row * K + k0) + cb);
    }
}

// ---------------------------------------------------------------------------
// GEMM: C[M,N] = alpha * A[M,K] @ B[N,K]^T   (fp16 x fp16 -> fp32/fp16)
// 128x128 CTA tile, 256 threads (8 warps 2x4), warp tile 64x32, 3 stages,
// 2 CTAs/SM. Two problems per launch.
// ---------------------------------------------------------------------------
__global__ __launch_bounds__(256, 2) void gemm_mma(GemmP p0, GemmP p1, int nblk0)
{
    extern __shared__ char dsm[];
    uint32_t base = (smem_u32(dsm) + 1023) & ~1023u;
    int tid = threadIdx.x, wid = tid >> 5, lane = tid & 31;
    int wm = wid >> 2, wn = wid & 3;         // 2 x 4 warp grid

    GemmP p = (blockIdx.x < nblk0) ? p0 : p1;
    int lb = (blockIdx.x < nblk0) ? blockIdx.x : blockIdx.x - nblk0;
    int bx = lb % p.tilesx, by = lb / p.tilesx;
    int K = p.K, N = p.N;

    const __half* Ab = p.A + (size_t)by * BM * K;
    const __half* Bb = p.B + (size_t)bx * BN * K;
    int nch = K / BK;

    float acc[4][4][4];
#pragma unroll
    for (int mi = 0; mi < 4; mi++)
#pragma unroll
        for (int ni = 0; ni < 4; ni++)
#pragma unroll
            for (int r = 0; r < 4; r++) acc[mi][ni][r] = 0.f;

    // prologue: fill stages 0 and 1
    load_stage(base, Ab, Bb, 0, K, tid);
    CP_COMMIT();
    load_stage(base + STAGE_BYTES, Ab, Bb, BK, K, tid);
    CP_COMMIT();

    // per-lane ldmatrix address components
    int ra  = wm * 64 + (lane & 15);                    // A row
    uint32_t cba = (uint32_t)(lane & 16);               // A byte col sel
    int rb  = wn * 32 + (lane & 7) + ((lane >> 1) & 8); // B row base
    uint32_t cbb = (uint32_t)((lane & 8) << 1);         // B byte col sel

    int slot = 0;
    for (int i = 0; i < nch; i++) {
        uint32_t sb = base + (uint32_t)slot * STAGE_BYTES;
        if (i + 2 < nch) { CP_WAIT(1); } else { CP_WAIT(0); }
        __syncthreads();
        if (i + 2 < nch) {  // refill the slot freed by chunk i-1
            int ns = slot + 2; if (ns >= NSTAGE) ns -= NSTAGE;
            load_stage(base + (uint32_t)ns * STAGE_BYTES,
                       Ab, Bb, (i + 2) * BK, K, tid);
            CP_COMMIT();
        }
#pragma unroll
        for (int ks = 0; ks < 4; ks++) {
            uint32_t kb = (uint32_t)(ks * 32);
            uint32_t ahr[4][4];
#pragma unroll
            for (int mi = 0; mi < 4; mi++) {
                uint32_t off = swz((uint32_t)((ra + mi * 16) * 128) + kb + cba);
                LDSM4(ahr[mi], sb + A_OFF + off);
            }
#pragma unroll
            for (int nb = 0; nb < 2; nb++) {
                uint32_t bh[4];
                uint32_t off = swz((uint32_t)((rb + nb * 16) * 128) + kb + cbb);
                LDSM4(bh, sb + B_OFF + off);
#pragma unroll
                for (int mi = 0; mi < 4; mi++) {
                    MMAF16(acc[mi][nb * 2],     ahr[mi], bh[0], bh[1]);
                    MMAF16(acc[mi][nb * 2 + 1], ahr[mi], bh[2], bh[3]);
                }
            }
        }
        if (++slot >= NSTAGE) slot = 0;
    }

    // epilogue
    int r0 = by * BM + wm * 64;
    int c0 = bx * BN + wn * 32;
    float alpha = p.alpha;
    if (p.chalf) {
        __half* Ch = (__half*)p.C;
#pragma unroll
        for (int mi = 0; mi < 4; mi++)
#pragma unroll
            for (int ni = 0; ni < 4; ni++) {
                int row = r0 + mi * 16 + (lane >> 2);
                int col = c0 + ni * 8 + (lane & 3) * 2;
                __half2 h0 = __floats2half2_rn(acc[mi][ni][0] * alpha,
                                               acc[mi][ni][1] * alpha);
                __half2 h1 = __floats2half2_rn(acc[mi][ni][2] * alpha,
                                               acc[mi][ni][3] * alpha);
                *(__half2*)(Ch + (size_t)row * N + col)       = h0;
                *(__half2*)(Ch + (size_t)(row + 8) * N + col) = h1;
            }
    } else {
        float* Cf = (float*)p.C;
#pragma unroll
        for (int mi = 0; mi < 4; mi++)
#pragma unroll
            for (int ni = 0; ni < 4; ni++) {
                int row = r0 + mi * 16 + (lane >> 2);
                int col = c0 + ni * 8 + (lane & 3) * 2;
                float2 v0 = make_float2(acc[mi][ni][0] * alpha, acc[mi][ni][1] * alpha);
                float2 v1 = make_float2(acc[mi][ni][2] * alpha, acc[mi][ni][3] * alpha);
                *(float2*)(Cf + (size_t)row * N + col)       = v0;
                *(float2*)(Cf + (size_t)(row + 8) * N + col) = v1;
            }
    }
}

// ---------------------------------------------------------------------------
// LayerNorm -> fp16 directly.
// ---------------------------------------------------------------------------
__global__ __launch_bounds__(256) void ln_kernel(
    const float* __restrict__ y, const float* __restrict__ w,
    const float* __restrict__ bia)
{
    int row = blockIdx.x;
    const float* x = y + (size_t)row * DIM;
    float v[8], s = 0.f, s2 = 0.f;
#pragma unroll
    for (int i = 0; i < 8; i++) {
        v[i] = x[threadIdx.x + i * 256];
        s += v[i]; s2 += v[i] * v[i];
    }
#pragma unroll
    for (int off = 16; off; off >>= 1) {
        s  += __shfl_down_sync(0xffffffffu, s, off);
        s2 += __shfl_down_sync(0xffffffffu, s2, off);
    }
    __shared__ float sm[2][8], stats[2];
    int lane = threadIdx.x & 31, wid = threadIdx.x >> 5;
    if (lane == 0) { sm[0][wid] = s; sm[1][wid] = s2; }
    __syncthreads();
    if (threadIdx.x == 0) {
        float ts = 0.f, ts2 = 0.f;
#pragma unroll
        for (int i = 0; i < 8; i++) { ts += sm[0][i]; ts2 += sm[1][i]; }
        float mu = ts / DIM, var = ts2 / DIM - mu * mu;
        stats[0] = mu; stats[1] = rsqrtf(var + LN_EPS);
    }
    __syncthreads();
    float mu = stats[0], rstd = stats[1];
#pragma unroll
    for (int i = 0; i < 8; i++) {
        int idx = threadIdx.x + i * 256;
        float val = (v[i] - mu) * rstd * w[idx] + bia[idx];
        g_yn[(size_t)row * DIM + idx] = __float2half(val);
    }
}

// ---------------------------------------------------------------------------
// fused prep: scan+build | media tohalf | 3 weight transposes, by block range.
// ---------------------------------------------------------------------------
__device__ __forceinline__ void do_transpose(
    const float* __restrict__ W, __half* __restrict__ Th,
    int K, int N, int tileIdx, float* tbuf)
{
    float (*t)[33] = (float(*)[33])tbuf;
    int tilesx = N / 32;
    int nb = (tileIdx % tilesx) * 32;
    int kb = (tileIdx / tilesx) * 32;
    int tx = threadIdx.x & 31, ty = threadIdx.x >> 5;
#pragma unroll
    for (int r = 0; r < 32; r += 8)
        t[ty + r][tx] = W[(size_t)(kb + ty + r) * N + nb + tx];
    __syncthreads();
#pragma unroll
    for (int r = 0; r < 32; r += 8) {
        float v = t[tx][ty + r] * WSCALE;
        Th[(size_t)(nb + ty + r) * K + kb + tx] = __float2half(v);
    }
}

__global__ __launch_bounds__(256) void prep_kernel(
    const void* __restrict__ locp, const float* __restrict__ media,
    const float* __restrict__ Wq, const float* __restrict__ Wkv,
    const float* __restrict__ Wout)
{
    __shared__ float tbuf[32 * 33];
    __shared__ int cnt_s[NM];
    __shared__ int wsum[8];
    int blk = blockIdx.x, tid = threadIdx.x;

    if (blk < PREP_SCAN) {
        const unsigned int* u = (const unsigned int*)locp;
        int mode;
        if (u[0] == 0x3F800000u) mode = 2;
        else if (u[64] & 0xFFu)  mode = 1;
        else                     mode = 0;
        int b = blk;
        if (tid < NM) cnt_s[tid] = 0;
        int v[8], s = 0;
#pragma unroll
        for (int i = 0; i < 8; i++) {
            int g = b * T_ + tid * 8 + i;
            int bit;
            if (mode == 1)      bit = ((const unsigned char*)locp)[g] != 0;
            else if (mode == 2) bit = ((const float*)locp)[g] != 0.0f;
            else                bit = ((const int*)locp)[g] != 0;
            v[i] = bit; s += bit;
        }
        int lane = tid & 31, wid = tid >> 5, pre = s;
#pragma unroll
        for (int off = 1; off < 32; off <<= 1) {
            int n = __shfl_up_sync(0xffffffffu, pre, off);
            if (lane >= off) pre += n;
        }
        if (lane == 31) wsum[wid] = pre;
        __syncthreads();
        int woff = 0;
        for (int w = 0; w < wid; w++) woff += wsum[w];
        int tt = woff + pre - s;
#pragma unroll
        for (int i = 0; i < 8; i++) {
            tt += v[i];
            if (tt >= 1 && tt <= NM) {
                int idx = atomicAdd(&cnt_s[tt - 1], 1);
                g_tok[(b * NM + tt - 1) * T_ + idx] = tid * 8 + i;
            }
        }
        __syncthreads();
        if (tid < NM) g_cnt[b * NM + tid] = cnt_s[tid];
    } else if (blk < PREP_SCAN + PREP_TOHALF) {
        int base = (blk - PREP_SCAN) * 2048;
#pragma unroll
        for (int i = 0; i < 8; i++) {
            int e = base + i * 256 + tid;
            g_m[e] = __float2half(media[e]);
        }
    } else if (blk < PREP_SCAN + PREP_TOHALF + PREP_TQ) {
        do_transpose(Wq, g_wq, DIM, INNER_,
                     blk - PREP_SCAN - PREP_TOHALF, tbuf);
    } else if (blk < PREP_SCAN + PREP_TOHALF + PREP_TQ + PREP_TK) {
        do_transpose(Wkv, g_wk, DIMV, 2 * INNER_,
                     blk - PREP_SCAN - PREP_TOHALF - PREP_TQ, tbuf);
    } else {
        do_transpose(Wout, g_wo, INNER_, DIM,
                     blk - PREP_SCAN - PREP_TOHALF - PREP_TQ - PREP_TK, tbuf);
    }
}

// ---------------------------------------------------------------------------
// masked attention on mma.sync. One CTA per (b, media-block, head), 128 thr
// (4 warps). K tile [key][dim] and transposed V tile [dim][key] in smem with
// the same SW128/ldmatrix recipe as the GEMM B operand. Each warp: 16 tokens
// per iteration; S-frags become P A-frags in registers (no smem round trip).
// ---------------------------------------------------------------------------
__global__ __launch_bounds__(128) void attn_kernel() {
    __shared__ __align__(128) char smv[ATQ_OFF + 4 * 2048];
    uint32_t sb = smem_u32(smv);
    int bm = blockIdx.x;
    int b = bm >> 3, m = bm & 7;
    int h = blockIdx.y;
    int tid = threadIdx.x, w = tid >> 5, lane = tid & 31;

    const __half* kvb = g_kv + (size_t)(b * J_ + m * NV) * (2 * INNER_);
    // K: [key][dim] rows, half2 copies (coalesced 64B per key row)
    for (int i = tid; i < NV * DH / 2; i += 128) {
        int key = i >> 5, dp = (i & 31) * 2;
        __half2 kx = *(const __half2*)(kvb + (size_t)key * (2 * INNER_) + h * DH + dp);
        *(__half2*)(smv + ATK_OFF + swz((uint32_t)(key * 128 + dp * 2))) = kx;
    }
    // V transposed: Vt[dim][key] (scattered stores, one-time)
    for (int i = tid; i < NV * DH; i += 128) {
        int key = i >> 6, d = i & 63;
        __half vx = kvb[(size_t)key * (2 * INNER_) + INNER_ + h * DH + d];
        *(__half*)(smv + ATV_OFF + swz((uint32_t)(d * 128 + key * 2))) = vx;
    }
    __syncthreads();

    int cnt = g_cnt[b * NM + m];
    const int* toklist = g_tok + (b * NM + m) * T_;
    uint32_t qbase = sb + ATQ_OFF + w * 2048;
    int rb  = (lane & 7) + ((lane >> 1) & 8);
    uint32_t cbb = (uint32_t)((lane & 8) << 1);
    int r = lane >> 2;

    for (int base = w * 16; base < cnt; base += 64) {
        // gather 16 token q-rows (fp16, 128B each) into this warp's tile
#pragma unroll
        for (int pqi = 0; pqi < 4; pqi++) {
            int u = lane + pqi * 32;
            int row = u >> 3, cb = (u & 7) * 16;
            int idx = base + row;
            int t = toklist[idx < cnt ? idx : cnt - 1];
            const char* src = (const char*)(g_q + (size_t)(b * T_ + t) * INNER_ + h * DH) + cb;
            *(int4*)(smv + ATQ_OFF + w * 2048 + swz((uint32_t)(row * 128 + cb))) =
                *(const int4*)src;
        }
        __syncwarp();

        // S = Q @ K^T  (16 x 64)
        float s[8][4];
#pragma unroll
        for (int nt = 0; nt < 8; nt++)
#pragma unroll
            for (int rr = 0; rr < 4; rr++) s[nt][rr] = 0.f;
#pragma unroll
        for (int kk = 0; kk < 4; kk++) {
            uint32_t kb = (uint32_t)(kk * 32);
            uint32_t aq[4];
            LDSM4(aq, qbase + swz((uint32_t)((lane & 15) * 128) + kb + (uint32_t)(lane & 16)));
#pragma unroll
            for (int nb = 0; nb < 4; nb++) {
                uint32_t bk[4];
                LDSM4(bk, sb + ATK_OFF + swz((uint32_t)((rb + nb * 16) * 128) + kb + cbb));
                MMAF16(s[nb * 2],     aq, bk[0], bk[1]);
                MMAF16(s[nb * 2 + 1], aq, bk[2], bk[3]);
            }
        }

        // softmax over the 64 keys (rows r and r+8 of this 16-token tile)
        float mx0 = -1e30f, mx1 = -1e30f;
#pragma unroll
        for (int nt = 0; nt < 8; nt++) {
            mx0 = fmaxf(mx0, fmaxf(s[nt][0], s[nt][1]));
            mx1 = fmaxf(mx1, fmaxf(s[nt][2], s[nt][3]));
        }
        mx0 = fmaxf(mx0, __shfl_xor_sync(0xffffffffu, mx0, 1));
        mx0 = fmaxf(mx0, __shfl_xor_sync(0xffffffffu, mx0, 2));
        mx1 = fmaxf(mx1, __shfl_xor_sync(0xffffffffu, mx1, 1));
        mx1 = fmaxf(mx1, __shfl_xor_sync(0xffffffffu, mx1, 2));
        float sum0 = 0.f, sum1 = 0.f;
#pragma unroll
        for (int nt = 0; nt < 8; nt++) {
            s[nt][0] = __expf(s[nt][0] - mx0);
            s[nt][1] = __expf(s[nt][1] - mx0);
            s[nt][2] = __expf(s[nt][2] - mx1);
            s[nt][3] = __expf(s[nt][3] - mx1);
            sum0 += s[nt][0] + s[nt][1];
            sum1 += s[nt][2] + s[nt][3];
        }
        sum0 += __shfl_xor_sync(0xffffffffu, sum0, 1);
        sum0 += __shfl_xor_sync(0xffffffffu, sum0, 2);
        sum1 += __shfl_xor_sync(0xffffffffu, sum1, 1);
        sum1 += __shfl_xor_sync(0xffffffffu, sum1, 2);
        float inv0 = 1.0f / sum0, inv1 = 1.0f / sum1;
        uint32_t pa[8], pb[8];   // P halves: rows r / r+8 per n-tile
#pragma unroll
        for (int nt = 0; nt < 8; nt++) {
            pa[nt] = h2pack(s[nt][0] * inv0, s[nt][1] * inv0);
            pb[nt] = h2pack(s[nt][2] * inv1, s[nt][3] * inv1);
        }

        // O = P @ V  (16 x 64) using Vt tiles; P frags straight from registers
        float o[8][4];
#pragma unroll
        for (int nt = 0; nt < 8; nt++)
#pragma unroll
            for (int rr = 0; rr < 4; rr++) o[nt][rr] = 0.f;
#pragma unroll
        for (int kk = 0; kk < 4; kk++) {
            uint32_t kb = (uint32_t)(kk * 32);
            uint32_t ap[4] = { pa[2 * kk], pb[2 * kk], pa[2 * kk + 1], pb[2 * kk + 1] };
#pragma unroll
            for (int nb = 0; nb < 4; nb++) {
                uint32_t bv[4];
                LDSM4(bv, sb + ATV_OFF + swz((uint32_t)((rb + nb * 16) * 128) + kb + cbb));
                MMAF16(o[nb * 2],     ap, bv[0], bv[1]);
                MMAF16(o[nb * 2 + 1], ap, bv[2], bv[3]);
            }
        }

        // store: rows r and r+8 -> tokens base+r, base+r+8
        int i0 = base + r, i1 = base + r + 8;
        if (i0 < cnt) {
            int t0 = toklist[i0];
            __half* dst = g_at + (size_t)(b * T_ + t0) * INNER_ + h * DH + (lane & 3) * 2;
#pragma unroll
            for (int nt = 0; nt < 8; nt++) {
                uint32_t pk = h2pack(o[nt][0], o[nt][1]);
                *(uint32_t*)(dst + nt * 8) = pk;
            }
        }
        if (i1 < cnt) {
            int t1 = toklist[i1];
            __half* dst = g_at + (size_t)(b * T_ + t1) * INNER_ + h * DH + (lane & 3) * 2;
#pragma unroll
            for (int nt = 0; nt < 8; nt++) {
                uint32_t pk = h2pack(o[nt][2], o[nt][3]);
                *(uint32_t*)(dst + nt * 8) = pk;
            }
        }
        __syncwarp();   // protect Qs tile before next gather
    }
}

// ---------------------------------------------------------------------------
extern "C" void kernel_launch(void* const* d_in, const int* in_sizes, int n_in,
                              void* d_out, int out_size)
{
    const float* y     = (const float*)d_in[0];
    const float* media = (const float*)d_in[1];
    const void*  loc   = d_in[2];
    const float* lnw   = (const float*)d_in[3];
    const float* lnb   = (const float*)d_in[4];
    const float* Wq    = (const float*)d_in[5];
    const float* Wkv   = (const float*)d_in[6];
    const float* Wout  = (const float*)d_in[7];
    float*       out   = (float*)d_out;

    static bool attr_set = false;   // host-side config only
    if (!attr_set) {
        cudaFuncSetAttribute(gemm_mma,
            cudaFuncAttributeMaxDynamicSharedMemorySize, SMEM_DYN);
        attr_set = true;
    }

    __half *yn, *m, *at, *wq, *wk, *wo, *q, *kv;
    cudaGetSymbolAddress((void**)&yn, g_yn);
    cudaGetSymbolAddress((void**)&m,  g_m);
    cudaGetSymbolAddress((void**)&at, g_at);
    cudaGetSymbolAddress((void**)&wq, g_wq);
    cudaGetSymbolAddress((void**)&wk, g_wk);
    cudaGetSymbolAddress((void**)&wo, g_wo);
    cudaGetSymbolAddress((void**)&q,  g_q);
    cudaGetSymbolAddress((void**)&kv, g_kv);

    ln_kernel<<<B_ * T_, 256>>>(y, lnw, lnb);
    prep_kernel<<<PREP_BLKS, 256>>>(loc, media, Wq, Wkv, Wout);

    // fused launch: GEMM1 (q fp16 out) + GEMM2 (kv fp16 out)
    GemmP p1 { yn, wq, (void*)q, INNER_, DIM, INNER_ / BN, 0.125f / WSCALE, 1 };
    int nblk1 = (INNER_ / BN) * ((B_ * T_) / BM);       // 512
    GemmP p2 { m, wk, (void*)kv, 2 * INNER_, DIMV, 2 * INNER_ / BN, 1.0f / WSCALE, 1 };
    int nblk2 = (2 * INNER_ / BN) * ((B_ * J_) / BM);   // 256
    gemm_mma<<<nblk1 + nblk2, 256, SMEM_DYN>>>(p1, p2, nblk1);

    attn_kernel<<<dim3(B_ * NM, HEADS_), 128>>>();

    // GEMM3: out = attn @ WoutT^T (fp32 out)
    GemmP p3 { at, wo, (void*)out, DIM, INNER_, DIM / BN, 1.0f / WSCALE, 0 };
    int nblk3 = (DIM / BN) * ((B_ * T_) / BM);          // 1024
    gemm_mma<<<nblk3, 256, SMEM_DYN>>>(p3, p3, nblk3);
}